// round 1
// baseline (speedup 1.0000x reference)
#include <cuda_runtime.h>

// Problem constants
#define B_TOTAL 131072
#define T_SEQ   5
#define I_DIM   13
#define H_DIM   256
#define G_DIM   1024   // 4*H
#define OUT_DIM 6

// Kernel config
#define BT      16     // batch rows per block
#define THREADS 256
#define HP      260    // padded pitch for h shared rows (avoids proj-phase bank conflicts)

// -------- device scratch (allocation-free rule: __device__ globals) --------
__device__ float g_Wt [H_DIM * G_DIM];  // transposed W_hh: [k][g]
__device__ float g_Wit[I_DIM * G_DIM];  // transposed W_ih: [i][g]
__device__ float g_bs [G_DIM];          // b_ih + b_hh

// ---------------------------------------------------------------------------
__global__ void prep_kernel(const float* __restrict__ W_ih,
                            const float* __restrict__ W_hh,
                            const float* __restrict__ b_ih,
                            const float* __restrict__ b_hh) {
    int idx = blockIdx.x * blockDim.x + threadIdx.x;
    int stride = gridDim.x * blockDim.x;
    for (int e = idx; e < H_DIM * G_DIM; e += stride) {
        int k = e / G_DIM, g = e % G_DIM;
        g_Wt[e] = W_hh[g * H_DIM + k];
    }
    for (int e = idx; e < I_DIM * G_DIM; e += stride) {
        int i = e / G_DIM, g = e % G_DIM;
        g_Wit[e] = W_ih[g * I_DIM + i];
    }
    for (int e = idx; e < G_DIM; e += stride)
        g_bs[e] = b_ih[e] + b_hh[e];
}

// ---- accurate fast activations (MUFU EX2/RCP path, err ~1e-6) -------------
__device__ __forceinline__ float sigmoid_f(float x) {
    // x = +large -> expf(-x)=0 -> 1 ; x = -large -> expf(-x)=inf -> 0. Safe.
    return 1.0f / (1.0f + __expf(-x));
}
__device__ __forceinline__ float tanh_f(float x) {
    float a = fabsf(x);
    float e = __expf(-2.0f * a);          // in (0,1], no overflow
    float r = (1.0f - e) / (1.0f + e);
    return copysignf(r, x);
}

// ---------------------------------------------------------------------------
__global__ __launch_bounds__(THREADS, 1)
void lstm_kernel(const float* __restrict__ x,    // [B, T, I]
                 const float* __restrict__ W1,   // [OUT, T*H]
                 const float* __restrict__ b1,   // [OUT]
                 float* __restrict__ out) {      // [B, OUT]
    __shared__ float h_s[2][BT][HP];
    __shared__ float x_s[BT][T_SEQ][I_DIM];

    const int tid = threadIdx.x;
    const int b0  = blockIdx.x * BT;
    const int hu  = tid;  // each thread owns one hidden unit (0..255)

    // Stage input tile into shared
    for (int e = tid; e < BT * T_SEQ * I_DIM; e += THREADS) {
        int b = e / (T_SEQ * I_DIM), r = e % (T_SEQ * I_DIM);
        x_s[b][r / I_DIM][r % I_DIM] = x[(size_t)(b0 + b) * (T_SEQ * I_DIM) + r];
    }
    // h0 = 0
    for (int e = tid; e < BT * HP; e += THREADS)
        (&h_s[0][0][0])[e] = 0.0f;

    // Per-thread gate biases (row hu of each of the 4 gates)
    float bsum[4];
    #pragma unroll
    for (int g = 0; g < 4; g++) bsum[g] = g_bs[g * H_DIM + hu];

    // Cell state: thread t owns c[b][hu] for all BT batch rows
    float c[BT];
    #pragma unroll
    for (int j = 0; j < BT; j++) c[j] = 0.0f;

    // Output-head ownership: threads 0..BT*OUT-1 each own one (b, o) pair
    const int  pb = tid / OUT_DIM, po = tid % OUT_DIM;
    const bool do_proj = (tid < BT * OUT_DIM);
    float oacc = 0.0f;

    __syncthreads();

    int cur = 0;
    for (int t = 0; t < T_SEQ; t++) {
        const int nxt = cur ^ 1;

        float acc[4][BT];
        #pragma unroll
        for (int g = 0; g < 4; g++)
            #pragma unroll
            for (int j = 0; j < BT; j++) acc[g][j] = bsum[g];

        // ---- input projection: K = 13 ----
        #pragma unroll
        for (int i = 0; i < I_DIM; i++) {
            const float w0 = g_Wit[i * G_DIM +             hu];
            const float w1 = g_Wit[i * G_DIM +     H_DIM + hu];
            const float w2 = g_Wit[i * G_DIM + 2 * H_DIM + hu];
            const float w3 = g_Wit[i * G_DIM + 3 * H_DIM + hu];
            #pragma unroll
            for (int j = 0; j < BT; j++) {
                const float xv = x_s[j][t][i];          // warp-broadcast LDS
                acc[0][j] = fmaf(xv, w0, acc[0][j]);
                acc[1][j] = fmaf(xv, w1, acc[1][j]);
                acc[2][j] = fmaf(xv, w2, acc[2][j]);
                acc[3][j] = fmaf(xv, w3, acc[3][j]);
            }
        }

        // ---- hidden projection: K = 256 (the hot loop) ----
        #pragma unroll 2
        for (int k = 0; k < H_DIM; k++) {
            const float w0 = g_Wt[k * G_DIM +             hu];   // coalesced
            const float w1 = g_Wt[k * G_DIM +     H_DIM + hu];
            const float w2 = g_Wt[k * G_DIM + 2 * H_DIM + hu];
            const float w3 = g_Wt[k * G_DIM + 3 * H_DIM + hu];
            #pragma unroll
            for (int j = 0; j < BT; j++) {
                const float hv = h_s[cur][j][k];        // warp-broadcast LDS
                acc[0][j] = fmaf(hv, w0, acc[0][j]);
                acc[1][j] = fmaf(hv, w1, acc[1][j]);
                acc[2][j] = fmaf(hv, w2, acc[2][j]);
                acc[3][j] = fmaf(hv, w3, acc[3][j]);
            }
        }

        // ---- gates, state update, write h(t) into the other buffer ----
        #pragma unroll
        for (int j = 0; j < BT; j++) {
            const float ig = sigmoid_f(acc[0][j]);
            const float fg = sigmoid_f(acc[1][j]);
            const float gg = tanh_f   (acc[2][j]);
            const float og = sigmoid_f(acc[3][j]);
            const float cn = fmaf(fg, c[j], ig * gg);
            c[j] = cn;
            h_s[nxt][j][hu] = og * tanh_f(cn);          // conflict-free STS
        }
        __syncthreads();   // h(t) complete & visible

        // ---- fold output head for this timestep (tiny) ----
        if (do_proj) {
            const float* w1p = W1 + (size_t)po * (T_SEQ * H_DIM) + t * H_DIM;
            float s = 0.0f;
            #pragma unroll 4
            for (int k = 0; k < H_DIM; k++)
                s = fmaf(h_s[nxt][pb][k], w1p[k], s);
            oacc += s;
        }
        cur = nxt;
        // No extra sync needed: next iter writes the *other* buffer; the buffer
        // the projection reads isn't re-written until after the next sync.
    }

    if (do_proj)
        out[(size_t)(b0 + pb) * OUT_DIM + po] = oacc + b1[po];
}

// ---------------------------------------------------------------------------
extern "C" void kernel_launch(void* const* d_in, const int* in_sizes, int n_in,
                              void* d_out, int out_size) {
    const float* x    = (const float*)d_in[0];  // input_seq [B,5,13]
    const float* W_ih = (const float*)d_in[1];  // [1024,13]
    const float* W_hh = (const float*)d_in[2];  // [1024,256]
    const float* b_ih = (const float*)d_in[3];  // [1024]
    const float* b_hh = (const float*)d_in[4];  // [1024]
    const float* W1   = (const float*)d_in[5];  // [6,1280]
    const float* b1   = (const float*)d_in[6];  // [6]
    float* out = (float*)d_out;                 // [B,6]

    prep_kernel<<<256, 256>>>(W_ih, W_hh, b_ih, b_hh);
    lstm_kernel<<<B_TOTAL / BT, THREADS>>>(x, W1, b1, out);
}